// round 2
// baseline (speedup 1.0000x reference)
#include <cuda_runtime.h>
#include <math.h>

#define NB 2
#define NTOK 4096
#define ROWS (NB*NTOK)

__device__ float g_Pqc[ROWS*512];
__device__ float g_Pqs[ROWS*512];
__device__ float g_Pkc[ROWS*512];
__device__ float g_Pvc[ROWS*512];
__device__ float g_Pks[ROWS*512];
__device__ float g_Pvs[ROWS*128];
__device__ float g_Pca[16*64*64];

// ---------- generic 128x128 SGEMM tile: C = A(MxK) @ W(OxK)^T ----------
template<int K, int O>
__device__ __forceinline__ void gemm_tile(const float* __restrict__ A,
                                          const float* __restrict__ W,
                                          float* __restrict__ C,
                                          int m0, int o0)
{
    __shared__ float As[8][132];
    __shared__ float Ws[8][132];
    int tid = threadIdx.x;
    int lr = tid >> 1;
    int lk = (tid & 1) << 2;
    const float* Ap = A + (size_t)(m0 + lr) * K + lk;
    const float* Wp = W + (size_t)(o0 + lr) * K + lk;
    int ty = tid >> 4, tx = tid & 15;
    int r0 = ty << 3, c0 = tx << 3;
    float acc[8][8];
    #pragma unroll
    for (int i = 0; i < 8; i++)
        #pragma unroll
        for (int j = 0; j < 8; j++) acc[i][j] = 0.f;

    #pragma unroll 1
    for (int k0 = 0; k0 < K; k0 += 8) {
        float4 av = *(const float4*)(Ap + k0);
        float4 wv = *(const float4*)(Wp + k0);
        __syncthreads();
        As[lk+0][lr] = av.x; As[lk+1][lr] = av.y;
        As[lk+2][lr] = av.z; As[lk+3][lr] = av.w;
        Ws[lk+0][lr] = wv.x; Ws[lk+1][lr] = wv.y;
        Ws[lk+2][lr] = wv.z; Ws[lk+3][lr] = wv.w;
        __syncthreads();
        #pragma unroll
        for (int k = 0; k < 8; k++) {
            float4 a0 = *(const float4*)&As[k][r0];
            float4 a1 = *(const float4*)&As[k][r0+4];
            float4 b0 = *(const float4*)&Ws[k][c0];
            float4 b1 = *(const float4*)&Ws[k][c0+4];
            float a[8] = {a0.x,a0.y,a0.z,a0.w,a1.x,a1.y,a1.z,a1.w};
            float b[8] = {b0.x,b0.y,b0.z,b0.w,b1.x,b1.y,b1.z,b1.w};
            #pragma unroll
            for (int i = 0; i < 8; i++)
                #pragma unroll
                for (int j = 0; j < 8; j++)
                    acc[i][j] = fmaf(a[i], b[j], acc[i][j]);
        }
    }
    #pragma unroll
    for (int i = 0; i < 8; i++) {
        float* cp = C + (size_t)(m0 + r0 + i) * O + o0 + c0;
        *(float4*)cp     = make_float4(acc[i][0],acc[i][1],acc[i][2],acc[i][3]);
        *(float4*)(cp+4) = make_float4(acc[i][4],acc[i][5],acc[i][6],acc[i][7]);
    }
}

__global__ __launch_bounds__(256) void gemm_proj(
    const float* __restrict__ s_in, const float* __restrict__ sh_in,
    const float* __restrict__ Wqs, const float* __restrict__ Wkc,
    const float* __restrict__ Wvc, const float* __restrict__ Wks,
    const float* __restrict__ Wqc)
{
    int job = blockIdx.x >> 2;
    int ot  = blockIdx.x & 3;
    int m0  = blockIdx.y << 7;
    const float* A; const float* W; float* C;
    switch (job) {
        case 0: A = sh_in; W = Wqs; C = g_Pqs; break;
        case 1: A = sh_in; W = Wkc; C = g_Pkc; break;
        case 2: A = sh_in; W = Wvc; C = g_Pvc; break;
        case 3: A = sh_in; W = Wks; C = g_Pks; break;
        default: A = s_in; W = Wqc; C = g_Pqc; break;
    }
    gemm_tile<512,512>(A, W, C, m0, ot << 7);
}

__global__ __launch_bounds__(256) void gemm_vs(
    const float* __restrict__ h_in, const float* __restrict__ Wvs)
{
    gemm_tile<128,128>(h_in, Wvs, g_Pvs, blockIdx.x << 7, 0);
}

// ---------- channel attention: S = Qc^T Kc (64x64), softmax rows ----------
__global__ __launch_bounds__(256) void ca_attn(const float* __restrict__ temp)
{
    __shared__ float Qs[32][68];
    __shared__ float Ks[32][68];
    __shared__ float Ss[64][68];
    int bh = blockIdx.x;
    int b = bh >> 3, h = bh & 7;
    const float* Qc = g_Pqc + ((size_t)b*NTOK + h*512) * 512;  // (4096,64) view
    const float* Kc = g_Pkc + ((size_t)b*NTOK + h*512) * 512;
    int tid = threadIdx.x;
    int lr = tid >> 3, lc = (tid & 7) << 3;
    int ti = tid >> 4, tj = tid & 15;
    int i0 = ti << 2, j0 = tj << 2;
    float acc[4][4];
    #pragma unroll
    for (int i = 0; i < 4; i++)
        #pragma unroll
        for (int j = 0; j < 4; j++) acc[i][j] = 0.f;

    #pragma unroll 1
    for (int nt = 0; nt < 128; nt++) {
        int nb = nt << 5;
        const float* qp = Qc + (size_t)(nb + lr)*64 + lc;
        const float* kp = Kc + (size_t)(nb + lr)*64 + lc;
        float4 q0 = *(const float4*)qp, q1 = *(const float4*)(qp+4);
        float4 k0 = *(const float4*)kp, k1 = *(const float4*)(kp+4);
        __syncthreads();
        *(float4*)&Qs[lr][lc]   = q0; *(float4*)&Qs[lr][lc+4] = q1;
        *(float4*)&Ks[lr][lc]   = k0; *(float4*)&Ks[lr][lc+4] = k1;
        __syncthreads();
        #pragma unroll 8
        for (int nn = 0; nn < 32; nn++) {
            float4 q = *(const float4*)&Qs[nn][i0];
            float4 k = *(const float4*)&Ks[nn][j0];
            float qa[4] = {q.x,q.y,q.z,q.w};
            float ka[4] = {k.x,k.y,k.z,k.w};
            #pragma unroll
            for (int i = 0; i < 4; i++)
                #pragma unroll
                for (int j = 0; j < 4; j++)
                    acc[i][j] = fmaf(qa[i], ka[j], acc[i][j]);
        }
    }
    #pragma unroll
    for (int i = 0; i < 4; i++)
        *(float4*)&Ss[i0+i][j0] = make_float4(acc[i][0],acc[i][1],acc[i][2],acc[i][3]);
    __syncthreads();
    if (tid < 64) {
        float scale = 0.125f * temp[h];
        float row[64];
        #pragma unroll
        for (int j = 0; j < 64; j++) row[j] = Ss[tid][j] * scale;
        float m = row[0];
        #pragma unroll
        for (int j = 1; j < 64; j++) m = fmaxf(m, row[j]);
        float sum = 0.f;
        #pragma unroll
        for (int j = 0; j < 64; j++) { row[j] = __expf(row[j]-m); sum += row[j]; }
        float inv = 1.f / sum;
        #pragma unroll
        for (int j = 0; j < 64; j++)
            g_Pca[((size_t)bh*64 + tid)*64 + j] = row[j]*inv;
    }
}

// ---------- channel out: X[i,n] = sum_j P[i,j] * Vc[n,j] ----------
__global__ __launch_bounds__(256) void ca_out(float* __restrict__ out)
{
    __shared__ float Pts[64][68];   // [j][i]
    __shared__ float Vt[64][68];    // [j][m]
    int mt = blockIdx.x;            // 64 tokens per tile
    int bh = blockIdx.y;
    int b = bh >> 3, h = bh & 7;
    int tid = threadIdx.x;
    {
        int i  = tid & 63;
        int jc = (tid >> 6) << 4;
        const float* pp = g_Pca + ((size_t)bh*64 + i)*64 + jc;
        #pragma unroll
        for (int t = 0; t < 4; t++) {
            float4 v = *(const float4*)(pp + t*4);
            Pts[jc+t*4+0][i] = v.x; Pts[jc+t*4+1][i] = v.y;
            Pts[jc+t*4+2][i] = v.z; Pts[jc+t*4+3][i] = v.w;
        }
    }
    {
        int mm = tid & 63;
        int jc = (tid >> 6) << 4;
        const float* vp = g_Pvc + ((size_t)b*NTOK + h*512)*512
                                + (size_t)(mt*64 + mm)*64 + jc;
        #pragma unroll
        for (int t = 0; t < 4; t++) {
            float4 v = *(const float4*)(vp + t*4);
            Vt[jc+t*4+0][mm] = v.x; Vt[jc+t*4+1][mm] = v.y;
            Vt[jc+t*4+2][mm] = v.z; Vt[jc+t*4+3][mm] = v.w;
        }
    }
    __syncthreads();
    int ig = tid >> 4, mg = tid & 15;
    int i0 = ig << 2, m0 = mg << 2;
    float acc[4][4];
    #pragma unroll
    for (int i = 0; i < 4; i++)
        #pragma unroll
        for (int j = 0; j < 4; j++) acc[i][j] = 0.f;
    #pragma unroll 8
    for (int j = 0; j < 64; j++) {
        float4 p = *(const float4*)&Pts[j][i0];
        float4 v = *(const float4*)&Vt[j][m0];
        float pa[4] = {p.x,p.y,p.z,p.w};
        float va[4] = {v.x,v.y,v.z,v.w};
        #pragma unroll
        for (int i = 0; i < 4; i++)
            #pragma unroll
            for (int m = 0; m < 4; m++)
                acc[i][m] = fmaf(pa[i], va[m], acc[i][m]);
    }
    // x_ca[b,h,i,n] -> out[b, h*512 + i*8 + n/512, n%512], n = mt*64 + m
    int rowoff  = mt >> 3;
    int colbase = (mt & 7)*64 + m0;
    #pragma unroll
    for (int i = 0; i < 4; i++) {
        int row = h*512 + (i0+i)*8 + rowoff;
        float* op = out + ((size_t)b*NTOK + row)*640 + colbase;
        *(float4*)op = make_float4(acc[i][0],acc[i][1],acc[i][2],acc[i][3]);
    }
}

// ---------- spatial branch: fused flash attention ----------
__global__ __launch_bounds__(256) void flash_sa(const float* __restrict__ temp2,
                                                float* __restrict__ out)
{
    extern __shared__ float sm[];
    float* Qst = sm;              // [64][132]  (i, r) pre-scaled
    float* Kst = Qst + 64*132;    // [64][36]   (i, j)
    float* Vsm = Kst + 64*36;     // [32][20]   (j, c)
    float* Psm = Vsm + 32*20;     // [128][36]  (r, j)

    int qt = blockIdx.x, bh = blockIdx.y;
    int b = bh >> 3, h = bh & 7;
    float scale = 0.125f * temp2[h];
    const float* Qb = g_Pqs + ((size_t)b*NTOK + h*512)*512;  // (4096,64)
    const float* Kb = g_Pks + ((size_t)b*NTOK + h*512)*512;
    const float* Vb = g_Pvs + ((size_t)b*NTOK + h*512)*128;  // (4096,16)
    int tid = threadIdx.x;

    {
        int r = tid >> 1, ic = (tid & 1) << 5;
        const float* qp = Qb + (size_t)(qt*128 + r)*64 + ic;
        #pragma unroll
        for (int t = 0; t < 8; t++) {
            float4 v = *(const float4*)(qp + t*4);
            int i = ic + t*4;
            Qst[(i+0)*132 + r] = v.x*scale;
            Qst[(i+1)*132 + r] = v.y*scale;
            Qst[(i+2)*132 + r] = v.z*scale;
            Qst[(i+3)*132 + r] = v.w*scale;
        }
    }

    int ty = tid >> 3, tx = tid & 7;
    int r0 = ty << 2, j0 = tx << 2, c0 = tx << 1;
    float m_r[4] = {-1e30f,-1e30f,-1e30f,-1e30f};
    float l_r[4] = {0.f,0.f,0.f,0.f};
    float Ov[4][2];
    #pragma unroll
    for (int r = 0; r < 4; r++) { Ov[r][0] = 0.f; Ov[r][1] = 0.f; }

    #pragma unroll 1
    for (int kc = 0; kc < 128; kc++) {
        int kb = kc << 5;
        __syncthreads();
        {
            int jj = tid & 31, ic = (tid >> 5) << 3;
            const float* kp = Kb + (size_t)(kb + jj)*64 + ic;
            float4 v0 = *(const float4*)kp, v1 = *(const float4*)(kp+4);
            Kst[(ic+0)*36+jj]=v0.x; Kst[(ic+1)*36+jj]=v0.y;
            Kst[(ic+2)*36+jj]=v0.z; Kst[(ic+3)*36+jj]=v0.w;
            Kst[(ic+4)*36+jj]=v1.x; Kst[(ic+5)*36+jj]=v1.y;
            Kst[(ic+6)*36+jj]=v1.z; Kst[(ic+7)*36+jj]=v1.w;
        }
        if (tid < 128) {
            int jj = tid >> 2, cc = (tid & 3) << 2;
            *(float4*)&Vsm[jj*20+cc] = *(const float4*)(Vb + (size_t)(kb+jj)*16 + cc);
        }
        __syncthreads();

        float acc[4][4];
        #pragma unroll
        for (int r = 0; r < 4; r++)
            #pragma unroll
            for (int c = 0; c < 4; c++) acc[r][c] = 0.f;
        #pragma unroll 4
        for (int i = 0; i < 64; i++) {
            float4 q = *(const float4*)&Qst[i*132 + r0];
            float4 k = *(const float4*)&Kst[i*36 + j0];
            float qa[4] = {q.x,q.y,q.z,q.w};
            float ka[4] = {k.x,k.y,k.z,k.w};
            #pragma unroll
            for (int r = 0; r < 4; r++)
                #pragma unroll
                for (int c = 0; c < 4; c++)
                    acc[r][c] = fmaf(qa[r], ka[c], acc[r][c]);
        }
        float rm[4], corr[4], rs[4];
        #pragma unroll
        for (int r = 0; r < 4; r++)
            rm[r] = fmaxf(fmaxf(acc[r][0],acc[r][1]), fmaxf(acc[r][2],acc[r][3]));
        #pragma unroll
        for (int s = 1; s < 8; s <<= 1)
            #pragma unroll
            for (int r = 0; r < 4; r++)
                rm[r] = fmaxf(rm[r], __shfl_xor_sync(0xffffffffu, rm[r], s));
        #pragma unroll
        for (int r = 0; r < 4; r++) {
            float mn = fmaxf(m_r[r], rm[r]);
            corr[r] = __expf(m_r[r] - mn);
            m_r[r] = mn;
            rs[r] = 0.f;
        }
        #pragma unroll
        for (int r = 0; r < 4; r++)
            #pragma unroll
            for (int c = 0; c < 4; c++) {
                float p = __expf(acc[r][c] - m_r[r]);
                Psm[(r0+r)*36 + j0 + c] = p;
                rs[r] += p;
            }
        #pragma unroll
        for (int s = 1; s < 8; s <<= 1)
            #pragma unroll
            for (int r = 0; r < 4; r++)
                rs[r] += __shfl_xor_sync(0xffffffffu, rs[r], s);
        #pragma unroll
        for (int r = 0; r < 4; r++) {
            l_r[r] = l_r[r]*corr[r] + rs[r];
            Ov[r][0] *= corr[r];
            Ov[r][1] *= corr[r];
        }
        __syncthreads();
        #pragma unroll
        for (int jb = 0; jb < 32; jb += 4) {
            float4 p0 = *(const float4*)&Psm[(r0+0)*36 + jb];
            float4 p1 = *(const float4*)&Psm[(r0+1)*36 + jb];
            float4 p2 = *(const float4*)&Psm[(r0+2)*36 + jb];
            float4 p3 = *(const float4*)&Psm[(r0+3)*36 + jb];
            float v0a = Vsm[(jb+0)*20+c0], v0b = Vsm[(jb+0)*20+c0+1];
            float v1a = Vsm[(jb+1)*20+c0], v1b = Vsm[(jb+1)*20+c0+1];
            float v2a = Vsm[(jb+2)*20+c0], v2b = Vsm[(jb+2)*20+c0+1];
            float v3a = Vsm[(jb+3)*20+c0], v3b = Vsm[(jb+3)*20+c0+1];
            Ov[0][0] = fmaf(p0.x,v0a, fmaf(p0.y,v1a, fmaf(p0.z,v2a, fmaf(p0.w,v3a, Ov[0][0]))));
            Ov[0][1] = fmaf(p0.x,v0b, fmaf(p0.y,v1b, fmaf(p0.z,v2b, fmaf(p0.w,v3b, Ov[0][1]))));
            Ov[1][0] = fmaf(p1.x,v0a, fmaf(p1.y,v1a, fmaf(p1.z,v2a, fmaf(p1.w,v3a, Ov[1][0]))));
            Ov[1][1] = fmaf(p1.x,v0b, fmaf(p1.y,v1b, fmaf(p1.z,v2b, fmaf(p1.w,v3b, Ov[1][1]))));
            Ov[2][0] = fmaf(p2.x,v0a, fmaf(p2.y,v1a, fmaf(p2.z,v2a, fmaf(p2.w,v3a, Ov[2][0]))));
            Ov[2][1] = fmaf(p2.x,v0b, fmaf(p2.y,v1b, fmaf(p2.z,v2b, fmaf(p2.w,v3b, Ov[2][1]))));
            Ov[3][0] = fmaf(p3.x,v0a, fmaf(p3.y,v1a, fmaf(p3.z,v2a, fmaf(p3.w,v3a, Ov[3][0]))));
            Ov[3][1] = fmaf(p3.x,v0b, fmaf(p3.y,v1b, fmaf(p3.z,v2b, fmaf(p3.w,v3b, Ov[3][1]))));
        }
    }
    // x_sa[b,h,n,c] -> out[b, h*512 + n/8, 512 + (n%8)*16 + c]
    #pragma unroll
    for (int r = 0; r < 4; r++) {
        float inv = 1.f / l_r[r];
        int n = qt*128 + r0 + r;
        int row = h*512 + (n >> 3);
        int colb = 512 + (n & 7)*16 + c0;
        float2 v; v.x = Ov[r][0]*inv; v.y = Ov[r][1]*inv;
        *(float2*)&out[((size_t)b*NTOK + row)*640 + colb] = v;
    }
}

extern "C" void kernel_launch(void* const* d_in, const int* in_sizes, int n_in,
                              void* d_out, int out_size)
{
    const float* s_in = (const float*)d_in[0];
    const float* h_in = (const float*)d_in[1];
    const float* sh   = (const float*)d_in[2];
    const float* t1   = (const float*)d_in[3];
    const float* t2   = (const float*)d_in[4];
    const float* Wqc  = (const float*)d_in[5];
    const float* Wqs  = (const float*)d_in[6];
    const float* Wkc  = (const float*)d_in[7];
    const float* Wvc  = (const float*)d_in[8];
    const float* Wks  = (const float*)d_in[9];
    const float* Wvs  = (const float*)d_in[10];
    float* out = (float*)d_out;

    const int FLASH_SMEM = (64*132 + 64*36 + 32*20 + 128*36) * sizeof(float); // 64000 B
    cudaFuncSetAttribute(flash_sa, cudaFuncAttributeMaxDynamicSharedMemorySize, FLASH_SMEM);

    gemm_proj<<<dim3(20,64), 256>>>(s_in, sh, Wqs, Wkc, Wvc, Wks, Wqc);
    gemm_vs<<<64, 256>>>(h_in, Wvs);
    ca_attn<<<16, 256>>>(t1);
    ca_out<<<dim3(64,16), 256>>>(out);
    flash_sa<<<dim3(32,16), 256, FLASH_SMEM>>>(t2, out);
}

// round 4
// speedup vs baseline: 2.1190x; 2.1190x over previous
#include <cuda_runtime.h>
#include <math.h>
#include <stdint.h>

#define NB 2
#define NTOK 4096

__device__ float g_Pqc[8192*512];
__device__ float g_Pqs[8192*512];
__device__ float g_Pkc[8192*512];
__device__ float g_Pvc[8192*512];
__device__ float g_Pks[8192*512];
__device__ float g_Pvs[8192*128];
__device__ float g_Sca[16*8*64*64];
__device__ float g_Pca[16*64*64];

// =================== helpers ===================
__device__ __forceinline__ uint32_t f2tf(float x) {
    uint32_t r; asm("cvt.rna.tf32.f32 %0, %1;" : "=r"(r) : "f"(x)); return r;
}
__device__ __forceinline__ float ex2f(float x) {
    float r; asm("ex2.approx.ftz.f32 %0, %1;" : "=f"(r) : "f"(x)); return r;
}
__device__ __forceinline__ void mma8(float* d, const uint32_t* a, uint32_t b0, uint32_t b1) {
    asm volatile(
        "mma.sync.aligned.m16n8k8.row.col.f32.tf32.tf32.f32 "
        "{%0,%1,%2,%3},{%4,%5,%6,%7},{%8,%9},{%0,%1,%2,%3};"
        : "+f"(d[0]), "+f"(d[1]), "+f"(d[2]), "+f"(d[3])
        : "r"(a[0]), "r"(a[1]), "r"(a[2]), "r"(a[3]), "r"(b0), "r"(b1));
}

// =================== fp32 SGEMM (projections) ===================
template<int K, int O>
__device__ __forceinline__ void gemm_tile(const float* __restrict__ A,
                                          const float* __restrict__ W,
                                          float* __restrict__ C,
                                          int m0, int o0)
{
    __shared__ float As[8][132];
    __shared__ float Ws[8][132];
    int tid = threadIdx.x;
    int lr = tid >> 1, lk = (tid & 1) << 2;
    const float* Ap = A + (size_t)(m0 + lr) * K + lk;
    const float* Wp = W + (size_t)(o0 + lr) * K + lk;
    int ty = tid >> 4, tx = tid & 15;
    int r0 = ty << 3, c0 = tx << 3;
    float acc[8][8];
    #pragma unroll
    for (int i = 0; i < 8; i++)
        #pragma unroll
        for (int j = 0; j < 8; j++) acc[i][j] = 0.f;
    #pragma unroll 1
    for (int k0 = 0; k0 < K; k0 += 8) {
        float4 av = *(const float4*)(Ap + k0);
        float4 wv = *(const float4*)(Wp + k0);
        __syncthreads();
        As[lk+0][lr] = av.x; As[lk+1][lr] = av.y; As[lk+2][lr] = av.z; As[lk+3][lr] = av.w;
        Ws[lk+0][lr] = wv.x; Ws[lk+1][lr] = wv.y; Ws[lk+2][lr] = wv.z; Ws[lk+3][lr] = wv.w;
        __syncthreads();
        #pragma unroll
        for (int k = 0; k < 8; k++) {
            float4 a0 = *(const float4*)&As[k][r0];
            float4 a1 = *(const float4*)&As[k][r0+4];
            float4 b0 = *(const float4*)&Ws[k][c0];
            float4 b1 = *(const float4*)&Ws[k][c0+4];
            float a[8] = {a0.x,a0.y,a0.z,a0.w,a1.x,a1.y,a1.z,a1.w};
            float b[8] = {b0.x,b0.y,b0.z,b0.w,b1.x,b1.y,b1.z,b1.w};
            #pragma unroll
            for (int i = 0; i < 8; i++)
                #pragma unroll
                for (int j = 0; j < 8; j++)
                    acc[i][j] = fmaf(a[i], b[j], acc[i][j]);
        }
    }
    #pragma unroll
    for (int i = 0; i < 8; i++) {
        float* cp = C + (size_t)(m0 + r0 + i) * O + o0 + c0;
        *(float4*)cp     = make_float4(acc[i][0],acc[i][1],acc[i][2],acc[i][3]);
        *(float4*)(cp+4) = make_float4(acc[i][4],acc[i][5],acc[i][6],acc[i][7]);
    }
}

__global__ __launch_bounds__(256) void gemm_proj(
    const float* __restrict__ s_in, const float* __restrict__ sh_in,
    const float* __restrict__ Wqs, const float* __restrict__ Wkc,
    const float* __restrict__ Wvc, const float* __restrict__ Wks,
    const float* __restrict__ Wqc)
{
    int job = blockIdx.x >> 2;
    int ot  = blockIdx.x & 3;
    int m0  = blockIdx.y << 7;
    const float* A; const float* W; float* C;
    switch (job) {
        case 0: A = sh_in; W = Wqs; C = g_Pqs; break;
        case 1: A = sh_in; W = Wkc; C = g_Pkc; break;
        case 2: A = sh_in; W = Wvc; C = g_Pvc; break;
        case 3: A = sh_in; W = Wks; C = g_Pks; break;
        default: A = s_in; W = Wqc; C = g_Pqc; break;
    }
    gemm_tile<512,512>(A, W, C, m0, ot << 7);
}

__global__ __launch_bounds__(256) void gemm_vs(
    const float* __restrict__ h_in, const float* __restrict__ Wvs)
{
    gemm_tile<128,128>(h_in, Wvs, g_Pvs, blockIdx.x << 7, 0);
}

// =================== channel attention ===================
__global__ __launch_bounds__(256) void ca_scores()
{
    __shared__ float Qs[32][68];
    __shared__ float Ks[32][68];
    int slice = blockIdx.x;
    int bh    = blockIdx.y;
    int b = bh >> 3, h = bh & 7;
    const float* Qc = g_Pqc + ((size_t)b*NTOK + h*512) * 512;
    const float* Kc = g_Pkc + ((size_t)b*NTOK + h*512) * 512;
    int tid = threadIdx.x;
    int lr = tid >> 3, lc = (tid & 7) << 3;
    int i0 = (tid >> 4) << 2, j0 = (tid & 15) << 2;
    float acc[4][4];
    #pragma unroll
    for (int i = 0; i < 4; i++)
        #pragma unroll
        for (int j = 0; j < 4; j++) acc[i][j] = 0.f;
    #pragma unroll 1
    for (int nt = 0; nt < 16; nt++) {
        int nb = slice*512 + (nt << 5);
        const float* qp = Qc + (size_t)(nb + lr)*64 + lc;
        const float* kp = Kc + (size_t)(nb + lr)*64 + lc;
        float4 q0 = *(const float4*)qp, q1 = *(const float4*)(qp+4);
        float4 k0 = *(const float4*)kp, k1 = *(const float4*)(kp+4);
        __syncthreads();
        *(float4*)&Qs[lr][lc] = q0; *(float4*)&Qs[lr][lc+4] = q1;
        *(float4*)&Ks[lr][lc] = k0; *(float4*)&Ks[lr][lc+4] = k1;
        __syncthreads();
        #pragma unroll 8
        for (int nn = 0; nn < 32; nn++) {
            float4 q = *(const float4*)&Qs[nn][i0];
            float4 k = *(const float4*)&Ks[nn][j0];
            float qa[4] = {q.x,q.y,q.z,q.w};
            float ka[4] = {k.x,k.y,k.z,k.w};
            #pragma unroll
            for (int i = 0; i < 4; i++)
                #pragma unroll
                for (int j = 0; j < 4; j++)
                    acc[i][j] = fmaf(qa[i], ka[j], acc[i][j]);
        }
    }
    float* dst = g_Sca + ((size_t)(bh*8 + slice)*64)*64;
    #pragma unroll
    for (int i = 0; i < 4; i++)
        *(float4*)&dst[(i0+i)*64 + j0] = make_float4(acc[i][0],acc[i][1],acc[i][2],acc[i][3]);
}

__global__ void ca_reduce(const float* __restrict__ temp)
{
    int bh = blockIdx.x;
    int h  = bh & 7;
    int i  = threadIdx.x;
    float scale = 0.125f * temp[h];
    float row[64];
    #pragma unroll
    for (int j = 0; j < 64; j++) {
        float s = 0.f;
        #pragma unroll
        for (int p = 0; p < 8; p++)
            s += g_Sca[((size_t)(bh*8+p)*64 + i)*64 + j];
        row[j] = s * scale;
    }
    float m = row[0];
    #pragma unroll
    for (int j = 1; j < 64; j++) m = fmaxf(m, row[j]);
    float sum = 0.f;
    #pragma unroll
    for (int j = 0; j < 64; j++) { row[j] = __expf(row[j]-m); sum += row[j]; }
    float inv = 1.f / sum;
    #pragma unroll
    for (int j = 0; j < 64; j++)
        g_Pca[((size_t)bh*64 + i)*64 + j] = row[j]*inv;
}

__global__ __launch_bounds__(256) void ca_out(float* __restrict__ out)
{
    __shared__ float Pts[64][68];
    __shared__ float Vt[64][68];
    int mt = blockIdx.x;
    int bh = blockIdx.y;
    int b = bh >> 3, h = bh & 7;
    int tid = threadIdx.x;
    {
        int i  = tid & 63;
        int jc = (tid >> 6) << 4;
        const float* pp = g_Pca + ((size_t)bh*64 + i)*64 + jc;
        #pragma unroll
        for (int t = 0; t < 4; t++) {
            float4 v = *(const float4*)(pp + t*4);
            Pts[jc+t*4+0][i] = v.x; Pts[jc+t*4+1][i] = v.y;
            Pts[jc+t*4+2][i] = v.z; Pts[jc+t*4+3][i] = v.w;
        }
    }
    {
        int mm = tid & 63;
        int jc = (tid >> 6) << 4;
        const float* vp = g_Pvc + ((size_t)b*NTOK + h*512)*512 + (size_t)(mt*64 + mm)*64 + jc;
        #pragma unroll
        for (int t = 0; t < 4; t++) {
            float4 v = *(const float4*)(vp + t*4);
            Vt[jc+t*4+0][mm] = v.x; Vt[jc+t*4+1][mm] = v.y;
            Vt[jc+t*4+2][mm] = v.z; Vt[jc+t*4+3][mm] = v.w;
        }
    }
    __syncthreads();
    int i0 = (tid >> 4) << 2, m0 = (tid & 15) << 2;
    float acc[4][4];
    #pragma unroll
    for (int i = 0; i < 4; i++)
        #pragma unroll
        for (int j = 0; j < 4; j++) acc[i][j] = 0.f;
    #pragma unroll 8
    for (int j = 0; j < 64; j++) {
        float4 p = *(const float4*)&Pts[j][i0];
        float4 v = *(const float4*)&Vt[j][m0];
        float pa[4] = {p.x,p.y,p.z,p.w};
        float va[4] = {v.x,v.y,v.z,v.w};
        #pragma unroll
        for (int i = 0; i < 4; i++)
            #pragma unroll
            for (int m = 0; m < 4; m++)
                acc[i][m] = fmaf(pa[i], va[m], acc[i][m]);
    }
    int rowoff  = mt >> 3;
    int colbase = (mt & 7)*64 + m0;
    #pragma unroll
    for (int i = 0; i < 4; i++) {
        int row = h*512 + (i0+i)*8 + rowoff;
        float* op = out + ((size_t)b*NTOK + row)*640 + colbase;
        *(float4*)op = make_float4(acc[i][0],acc[i][1],acc[i][2],acc[i][3]);
    }
}

// =================== spatial flash attention: mma.sync tf32 ===================
// dyn smem (floats): K[2][64][68] @0, V[2][64][20] @8704, P[128][68] @11264
#define KSTR 68
#define VSTR 20
#define KOFF(b) ((b)*4352)
#define VOFF(b) (8704 + (b)*1280)
#define POFF 11264
#define FSMEM ((11264 + 128*68) * 4)   // 79872 bytes

__device__ __forceinline__ void load_kchunk(float* sm, const float* __restrict__ Kb,
                                            int kb, int tid, int buf)
{
    int j = tid >> 2, cg = (tid & 3) << 4;
    const float* kp = Kb + (size_t)(kb + j)*64 + cg;
    float* dst = sm + KOFF(buf) + j*KSTR + cg;
    #pragma unroll
    for (int t = 0; t < 4; t++) {
        float4 v = *(const float4*)(kp + t*4);
        float4 o;
        o.x = __uint_as_float(f2tf(v.x)); o.y = __uint_as_float(f2tf(v.y));
        o.z = __uint_as_float(f2tf(v.z)); o.w = __uint_as_float(f2tf(v.w));
        *(float4*)(dst + t*4) = o;
    }
}

__device__ __forceinline__ void load_vchunk(float* sm, const float* __restrict__ Vb,
                                            int kb, int tid, int buf)
{
    if (tid < 128) {
        int j = tid >> 1, cv = (tid & 1) << 3;
        const float* vp = Vb + (size_t)(kb + j)*16 + cv;
        float* dst = sm + VOFF(buf) + j*VSTR + cv;
        #pragma unroll
        for (int t = 0; t < 2; t++) {
            float4 v = *(const float4*)(vp + t*4);
            float4 o;
            o.x = __uint_as_float(f2tf(v.x)); o.y = __uint_as_float(f2tf(v.y));
            o.z = __uint_as_float(f2tf(v.z)); o.w = __uint_as_float(f2tf(v.w));
            *(float4*)(dst + t*4) = o;
        }
    }
}

__global__ __launch_bounds__(256, 1) void flash_mma(const float* __restrict__ t2,
                                                    float* __restrict__ out)
{
    extern __shared__ float sm[];
    int tid = threadIdx.x, w = tid >> 5, lane = tid & 31;
    int g = lane >> 2, tg = lane & 3;
    int qt = blockIdx.x, bh = blockIdx.y;
    int b = bh >> 3, h = bh & 7;
    const float* Qb = g_Pqs + ((size_t)b*NTOK + h*512)*512;   // (4096,64)
    const float* Kb = g_Pks + ((size_t)b*NTOK + h*512)*512;
    const float* Vb = g_Pvs + ((size_t)b*NTOK + h*512)*128;   // (4096,16)
    float qscale = 0.125f * t2[h] * 1.4426950408889634f;

    // Q fragments (registers), rows q0+g / q0+g+8, pre-scaled tf32
    int q0 = w << 4;
    uint32_t qa[8][4];
    {
        const float* qr0 = Qb + (size_t)(qt*128 + q0 + g)*64;
        const float* qr1 = qr0 + 8*64;
        #pragma unroll
        for (int ks = 0; ks < 8; ks++) {
            qa[ks][0] = f2tf(qr0[ks*8 + tg]     * qscale);
            qa[ks][1] = f2tf(qr1[ks*8 + tg]     * qscale);
            qa[ks][2] = f2tf(qr0[ks*8 + tg + 4] * qscale);
            qa[ks][3] = f2tf(qr1[ks*8 + tg + 4] * qscale);
        }
    }

    float Ofr[2][4];
    #pragma unroll
    for (int n = 0; n < 2; n++)
        #pragma unroll
        for (int e = 0; e < 4; e++) Ofr[n][e] = 0.f;
    float l0 = 0.f, l1 = 0.f;

    load_kchunk(sm, Kb, 0, tid, 0);
    load_vchunk(sm, Vb, 0, tid, 0);
    __syncthreads();

    float* Psm = sm + POFF;
    uint32_t prow0 = (q0 + g)*KSTR, prow1 = (q0 + g + 8)*KSTR;

    #pragma unroll 1
    for (int c = 0; c < 64; c++) {
        int cur = c & 1;
        if (c < 63) {
            load_kchunk(sm, Kb, (c+1) << 6, tid, cur ^ 1);
            load_vchunk(sm, Vb, (c+1) << 6, tid, cur ^ 1);
        }
        const uint32_t* Kc = (const uint32_t*)(sm + KOFF(cur));
        const uint32_t* Vc = (const uint32_t*)(sm + VOFF(cur));

        // ---- S = Q @ K^T : 8 n-tiles x 8 k-steps ----
        float sfr[8][4];
        #pragma unroll
        for (int nt = 0; nt < 8; nt++) {
            sfr[nt][0] = sfr[nt][1] = sfr[nt][2] = sfr[nt][3] = 0.f;
            const uint32_t* krow = Kc + (nt*8 + g)*KSTR;   // key = nt*8+g
            #pragma unroll
            for (int ks = 0; ks < 8; ks++)
                mma8(sfr[nt], qa[ks], krow[ks*8 + tg], krow[ks*8 + tg + 4]);
        }
        // ---- softmax (fixed shift, base-2) ----
        float rs0 = 0.f, rs1 = 0.f;
        #pragma unroll
        for (int nt = 0; nt < 8; nt++) {
            float p0 = ex2f(sfr[nt][0]), p1 = ex2f(sfr[nt][1]);
            float p2 = ex2f(sfr[nt][2]), p3 = ex2f(sfr[nt][3]);
            rs0 += p0 + p1; rs1 += p2 + p3;
            float2 v0, v1;
            v0.x = __uint_as_float(f2tf(p0)); v0.y = __uint_as_float(f2tf(p1));
            v1.x = __uint_as_float(f2tf(p2)); v1.y = __uint_as_float(f2tf(p3));
            *(float2*)&Psm[prow0 + nt*8 + 2*tg] = v0;
            *(float2*)&Psm[prow1 + nt*8 + 2*tg] = v1;
        }
        rs0 += __shfl_xor_sync(0xffffffffu, rs0, 1);
        rs0 += __shfl_xor_sync(0xffffffffu, rs0, 2);
        rs1 += __shfl_xor_sync(0xffffffffu, rs1, 1);
        rs1 += __shfl_xor_sync(0xffffffffu, rs1, 2);
        l0 += rs0; l1 += rs1;
        __syncthreads();   // P ready; next K/V stores drained

        // ---- O += P @ V : k = 64 keys, n = 16 ----
        const uint32_t* Pu = (const uint32_t*)Psm;
        #pragma unroll
        for (int ks = 0; ks < 8; ks++) {
            uint32_t ap[4];
            ap[0] = Pu[prow0 + ks*8 + tg];
            ap[1] = Pu[prow1 + ks*8 + tg];
            ap[2] = Pu[prow0 + ks*8 + tg + 4];
            ap[3] = Pu[prow1 + ks*8 + tg + 4];
            const uint32_t* v0 = Vc + (ks*8 + tg)*VSTR;
            const uint32_t* v1 = Vc + (ks*8 + tg + 4)*VSTR;
            mma8(Ofr[0], ap, v0[g],     v1[g]);
            mma8(Ofr[1], ap, v0[g + 8], v1[g + 8]);
        }
        __syncthreads();   // PV reads done before P / cur-buffer overwrite
    }

    // ---- epilogue: divide by row sums, write with reshape map ----
    float inv0 = 1.f / l0, inv1 = 1.f / l1;
    int n_g  = qt*128 + q0 + g;
    int n_g8 = n_g + 8;
    float* op0 = out + ((size_t)b*NTOK + h*512 + (n_g  >> 3))*640 + 512 + (n_g  & 7)*16;
    float* op1 = out + ((size_t)b*NTOK + h*512 + (n_g8 >> 3))*640 + 512 + (n_g8 & 7)*16;
    #pragma unroll
    for (int nt = 0; nt < 2; nt++) {
        int cbase = nt*8 + 2*tg;
        float2 a, c2;
        a.x  = Ofr[nt][0]*inv0; a.y  = Ofr[nt][1]*inv0;
        c2.x = Ofr[nt][2]*inv1; c2.y = Ofr[nt][3]*inv1;
        *(float2*)(op0 + cbase) = a;
        *(float2*)(op1 + cbase) = c2;
    }
}

// =================== launch ===================
extern "C" void kernel_launch(void* const* d_in, const int* in_sizes, int n_in,
                              void* d_out, int out_size)
{
    const float* s_in = (const float*)d_in[0];
    const float* h_in = (const float*)d_in[1];
    const float* sh   = (const float*)d_in[2];
    const float* t1   = (const float*)d_in[3];
    const float* t2   = (const float*)d_in[4];
    const float* Wqc  = (const float*)d_in[5];
    const float* Wqs  = (const float*)d_in[6];
    const float* Wkc  = (const float*)d_in[7];
    const float* Wvc  = (const float*)d_in[8];
    const float* Wks  = (const float*)d_in[9];
    const float* Wvs  = (const float*)d_in[10];
    float* out = (float*)d_out;

    cudaFuncSetAttribute(flash_mma, cudaFuncAttributeMaxDynamicSharedMemorySize, FSMEM);

    gemm_proj<<<dim3(20,64), 256>>>(s_in, sh, Wqs, Wkc, Wvc, Wks, Wqc);
    gemm_vs<<<64, 256>>>(h_in, Wvs);
    flash_mma<<<dim3(32,16), 256, FSMEM>>>(t2, out);
    ca_scores<<<dim3(8,16), 256>>>();
    ca_reduce<<<16, 64>>>(t1);
    ca_out<<<dim3(64,16), 256>>>(out);
}

// round 5
// speedup vs baseline: 2.8269x; 1.3341x over previous
#include <cuda_runtime.h>
#include <math.h>
#include <stdint.h>

#define NB 2
#define NTOK 4096

__device__ float g_Pqc[8192*512];
__device__ float g_Pqs[8192*512];
__device__ float g_Pkc[8192*512];
__device__ float g_Pvc[8192*512];
__device__ float g_Pks[8192*512];
__device__ float g_Pvs[8192*128];
__device__ float g_Sca[16*16*64*64];
__device__ float g_Pca[16*64*64];

// =================== helpers ===================
__device__ __forceinline__ uint32_t f2tf(float x) {
    uint32_t r; asm("cvt.rna.tf32.f32 %0, %1;" : "=r"(r) : "f"(x)); return r;
}
__device__ __forceinline__ float ex2f(float x) {
    float r; asm("ex2.approx.ftz.f32 %0, %1;" : "=f"(r) : "f"(x)); return r;
}
__device__ __forceinline__ void mma8(float* d, const uint32_t* a, uint32_t b0, uint32_t b1) {
    asm volatile(
        "mma.sync.aligned.m16n8k8.row.col.f32.tf32.tf32.f32 "
        "{%0,%1,%2,%3},{%4,%5,%6,%7},{%8,%9},{%0,%1,%2,%3};"
        : "+f"(d[0]), "+f"(d[1]), "+f"(d[2]), "+f"(d[3])
        : "r"(a[0]), "r"(a[1]), "r"(a[2]), "r"(a[3]), "r"(b0), "r"(b1));
}

// =================== tf32 tensor-core GEMM: C = A(MxK) @ W(OxK)^T ===================
// 128x128 CTA tile, K-chunk 16, 8 warps of 64x32, single smem buffer + reg prefetch.
template<int K, int O>
__device__ __forceinline__ void gemm_tc_tile(const float* __restrict__ A,
                                             const float* __restrict__ W,
                                             float* __restrict__ C,
                                             int m0, int o0)
{
    __shared__ float sA[128*20];
    __shared__ float sW[128*20];
    const int NC = K / 16;
    int tid = threadIdx.x, w = tid >> 5, lane = tid & 31;
    int g = lane >> 2, tg = lane & 3;
    int wm = w >> 2, wn = w & 3;               // warp tile: rows wm*64, cols wn*32
    int pr = tid >> 1, pc = (tid & 1) << 3;    // prefetch: row pr, cols pc..pc+7
    const float* Ap = A + (size_t)(m0 + pr) * K + pc;
    const float* Wp = W + (size_t)(o0 + pr) * K + pc;

    float acc[4][4][4];
    #pragma unroll
    for (int mt = 0; mt < 4; mt++)
        #pragma unroll
        for (int nt = 0; nt < 4; nt++)
            #pragma unroll
            for (int e = 0; e < 4; e++) acc[mt][nt][e] = 0.f;

    float4 ra0 = *(const float4*)Ap, ra1 = *(const float4*)(Ap + 4);
    float4 rw0 = *(const float4*)Wp, rw1 = *(const float4*)(Wp + 4);
    uint32_t* uAs = (uint32_t*)sA;
    uint32_t* uWs = (uint32_t*)sW;
    int srow = pr*20 + pc;

    #pragma unroll 1
    for (int c = 0; c < NC; c++) {
        __syncthreads();
        uAs[srow+0]=f2tf(ra0.x); uAs[srow+1]=f2tf(ra0.y); uAs[srow+2]=f2tf(ra0.z); uAs[srow+3]=f2tf(ra0.w);
        uAs[srow+4]=f2tf(ra1.x); uAs[srow+5]=f2tf(ra1.y); uAs[srow+6]=f2tf(ra1.z); uAs[srow+7]=f2tf(ra1.w);
        uWs[srow+0]=f2tf(rw0.x); uWs[srow+1]=f2tf(rw0.y); uWs[srow+2]=f2tf(rw0.z); uWs[srow+3]=f2tf(rw0.w);
        uWs[srow+4]=f2tf(rw1.x); uWs[srow+5]=f2tf(rw1.y); uWs[srow+6]=f2tf(rw1.z); uWs[srow+7]=f2tf(rw1.w);
        __syncthreads();
        if (c + 1 < NC) {
            const float* ap = Ap + (c+1)*16;
            const float* wp = Wp + (c+1)*16;
            ra0 = *(const float4*)ap; ra1 = *(const float4*)(ap + 4);
            rw0 = *(const float4*)wp; rw1 = *(const float4*)(wp + 4);
        }
        #pragma unroll
        for (int ks = 0; ks < 2; ks++) {
            uint32_t af[4][4], bf[4][2];
            #pragma unroll
            for (int mt = 0; mt < 4; mt++) {
                int rb = wm*64 + mt*16;
                af[mt][0] = uAs[(rb+g  )*20 + ks*8 + tg];
                af[mt][1] = uAs[(rb+g+8)*20 + ks*8 + tg];
                af[mt][2] = uAs[(rb+g  )*20 + ks*8 + tg + 4];
                af[mt][3] = uAs[(rb+g+8)*20 + ks*8 + tg + 4];
            }
            #pragma unroll
            for (int nt = 0; nt < 4; nt++) {
                int rb = wn*32 + nt*8 + g;
                bf[nt][0] = uWs[rb*20 + ks*8 + tg];
                bf[nt][1] = uWs[rb*20 + ks*8 + tg + 4];
            }
            #pragma unroll
            for (int mt = 0; mt < 4; mt++)
                #pragma unroll
                for (int nt = 0; nt < 4; nt++)
                    mma8(acc[mt][nt], af[mt], bf[nt][0], bf[nt][1]);
        }
    }
    #pragma unroll
    for (int mt = 0; mt < 4; mt++) {
        int r = m0 + wm*64 + mt*16 + g;
        #pragma unroll
        for (int nt = 0; nt < 4; nt++) {
            float* cp = C + (size_t)r*O + o0 + wn*32 + nt*8 + 2*tg;
            *(float2*)cp         = make_float2(acc[mt][nt][0], acc[mt][nt][1]);
            *(float2*)(cp + 8*O) = make_float2(acc[mt][nt][2], acc[mt][nt][3]);
        }
    }
}

__global__ __launch_bounds__(256) void gemm_proj_tc(
    const float* __restrict__ s_in, const float* __restrict__ sh_in,
    const float* __restrict__ Wqs, const float* __restrict__ Wkc,
    const float* __restrict__ Wvc, const float* __restrict__ Wks,
    const float* __restrict__ Wqc)
{
    int job = blockIdx.x >> 2;
    int ot  = blockIdx.x & 3;
    int m0  = blockIdx.y << 7;
    const float* A; const float* W; float* C;
    switch (job) {
        case 0: A = sh_in; W = Wqs; C = g_Pqs; break;
        case 1: A = sh_in; W = Wkc; C = g_Pkc; break;
        case 2: A = sh_in; W = Wvc; C = g_Pvc; break;
        case 3: A = sh_in; W = Wks; C = g_Pks; break;
        default: A = s_in; W = Wqc; C = g_Pqc; break;
    }
    gemm_tc_tile<512,512>(A, W, C, m0, ot << 7);
}

__global__ __launch_bounds__(256) void gemm_vs_tc(
    const float* __restrict__ h_in, const float* __restrict__ Wvs)
{
    gemm_tc_tile<128,128>(h_in, Wvs, g_Pvs, blockIdx.x << 7, 0);
}

// =================== channel attention ===================
__global__ __launch_bounds__(256) void ca_scores()
{
    __shared__ float Qs[32][68];
    __shared__ float Ks[32][68];
    int slice = blockIdx.x;   // 0..15 (256 tokens each)
    int bh    = blockIdx.y;
    int b = bh >> 3, h = bh & 7;
    const float* Qc = g_Pqc + ((size_t)b*NTOK + h*512) * 512;
    const float* Kc = g_Pkc + ((size_t)b*NTOK + h*512) * 512;
    int tid = threadIdx.x;
    int lr = tid >> 3, lc = (tid & 7) << 3;
    int i0 = (tid >> 4) << 2, j0 = (tid & 15) << 2;
    float acc[4][4];
    #pragma unroll
    for (int i = 0; i < 4; i++)
        #pragma unroll
        for (int j = 0; j < 4; j++) acc[i][j] = 0.f;
    #pragma unroll 1
    for (int nt = 0; nt < 8; nt++) {
        int nb = slice*256 + (nt << 5);
        const float* qp = Qc + (size_t)(nb + lr)*64 + lc;
        const float* kp = Kc + (size_t)(nb + lr)*64 + lc;
        float4 q0 = *(const float4*)qp, q1 = *(const float4*)(qp+4);
        float4 k0 = *(const float4*)kp, k1 = *(const float4*)(kp+4);
        __syncthreads();
        *(float4*)&Qs[lr][lc] = q0; *(float4*)&Qs[lr][lc+4] = q1;
        *(float4*)&Ks[lr][lc] = k0; *(float4*)&Ks[lr][lc+4] = k1;
        __syncthreads();
        #pragma unroll 8
        for (int nn = 0; nn < 32; nn++) {
            float4 q = *(const float4*)&Qs[nn][i0];
            float4 k = *(const float4*)&Ks[nn][j0];
            float qa[4] = {q.x,q.y,q.z,q.w};
            float ka[4] = {k.x,k.y,k.z,k.w};
            #pragma unroll
            for (int i = 0; i < 4; i++)
                #pragma unroll
                for (int j = 0; j < 4; j++)
                    acc[i][j] = fmaf(qa[i], ka[j], acc[i][j]);
        }
    }
    float* dst = g_Sca + ((size_t)(bh*16 + slice)*64)*64;
    #pragma unroll
    for (int i = 0; i < 4; i++)
        *(float4*)&dst[(i0+i)*64 + j0] = make_float4(acc[i][0],acc[i][1],acc[i][2],acc[i][3]);
}

__global__ void ca_reduce(const float* __restrict__ temp)
{
    int bh = blockIdx.x;
    int h  = bh & 7;
    int i  = threadIdx.x;
    float scale = 0.125f * temp[h];
    float row[64];
    #pragma unroll
    for (int j = 0; j < 64; j++) {
        float s = 0.f;
        #pragma unroll
        for (int p = 0; p < 16; p++)
            s += g_Sca[((size_t)(bh*16+p)*64 + i)*64 + j];
        row[j] = s * scale;
    }
    float m = row[0];
    #pragma unroll
    for (int j = 1; j < 64; j++) m = fmaxf(m, row[j]);
    float sum = 0.f;
    #pragma unroll
    for (int j = 0; j < 64; j++) { row[j] = __expf(row[j]-m); sum += row[j]; }
    float inv = 1.f / sum;
    #pragma unroll
    for (int j = 0; j < 64; j++)
        g_Pca[((size_t)bh*64 + i)*64 + j] = row[j]*inv;
}

__global__ __launch_bounds__(256) void ca_out(float* __restrict__ out)
{
    __shared__ float Pts[64][68];
    __shared__ float Vt[64][68];
    int mt = blockIdx.x;
    int bh = blockIdx.y;
    int b = bh >> 3, h = bh & 7;
    int tid = threadIdx.x;
    {
        int i  = tid & 63;
        int jc = (tid >> 6) << 4;
        const float* pp = g_Pca + ((size_t)bh*64 + i)*64 + jc;
        #pragma unroll
        for (int t = 0; t < 4; t++) {
            float4 v = *(const float4*)(pp + t*4);
            Pts[jc+t*4+0][i] = v.x; Pts[jc+t*4+1][i] = v.y;
            Pts[jc+t*4+2][i] = v.z; Pts[jc+t*4+3][i] = v.w;
        }
    }
    {
        int mm = tid & 63;
        int jc = (tid >> 6) << 4;
        const float* vp = g_Pvc + ((size_t)b*NTOK + h*512)*512 + (size_t)(mt*64 + mm)*64 + jc;
        #pragma unroll
        for (int t = 0; t < 4; t++) {
            float4 v = *(const float4*)(vp + t*4);
            Vt[jc+t*4+0][mm] = v.x; Vt[jc+t*4+1][mm] = v.y;
            Vt[jc+t*4+2][mm] = v.z; Vt[jc+t*4+3][mm] = v.w;
        }
    }
    __syncthreads();
    int i0 = (tid >> 4) << 2, m0 = (tid & 15) << 2;
    float acc[4][4];
    #pragma unroll
    for (int i = 0; i < 4; i++)
        #pragma unroll
        for (int j = 0; j < 4; j++) acc[i][j] = 0.f;
    #pragma unroll 8
    for (int j = 0; j < 64; j++) {
        float4 p = *(const float4*)&Pts[j][i0];
        float4 v = *(const float4*)&Vt[j][m0];
        float pa[4] = {p.x,p.y,p.z,p.w};
        float va[4] = {v.x,v.y,v.z,v.w};
        #pragma unroll
        for (int i = 0; i < 4; i++)
            #pragma unroll
            for (int m = 0; m < 4; m++)
                acc[i][m] = fmaf(pa[i], va[m], acc[i][m]);
    }
    int rowoff  = mt >> 3;
    int colbase = (mt & 7)*64 + m0;
    #pragma unroll
    for (int i = 0; i < 4; i++) {
        int row = h*512 + (i0+i)*8 + rowoff;
        float* op = out + ((size_t)b*NTOK + row)*640 + colbase;
        *(float4*)op = make_float4(acc[i][0],acc[i][1],acc[i][2],acc[i][3]);
    }
}

// =================== spatial flash attention: mma.sync tf32 ===================
#define KSTR 68
#define VSTR 20
#define KOFF(b) ((b)*4352)
#define VOFF(b) (8704 + (b)*1280)
#define POFF 11264
#define FSMEM ((11264 + 128*68) * 4)

__device__ __forceinline__ void load_kchunk(float* sm, const float* __restrict__ Kb,
                                            int kb, int tid, int buf)
{
    int j = tid >> 2, cg = (tid & 3) << 4;
    const float* kp = Kb + (size_t)(kb + j)*64 + cg;
    float* dst = sm + KOFF(buf) + j*KSTR + cg;
    #pragma unroll
    for (int t = 0; t < 4; t++) {
        float4 v = *(const float4*)(kp + t*4);
        float4 o;
        o.x = __uint_as_float(f2tf(v.x)); o.y = __uint_as_float(f2tf(v.y));
        o.z = __uint_as_float(f2tf(v.z)); o.w = __uint_as_float(f2tf(v.w));
        *(float4*)(dst + t*4) = o;
    }
}

__device__ __forceinline__ void load_vchunk(float* sm, const float* __restrict__ Vb,
                                            int kb, int tid, int buf)
{
    if (tid < 128) {
        int j = tid >> 1, cv = (tid & 1) << 3;
        const float* vp = Vb + (size_t)(kb + j)*16 + cv;
        float* dst = sm + VOFF(buf) + j*VSTR + cv;
        #pragma unroll
        for (int t = 0; t < 2; t++) {
            float4 v = *(const float4*)(vp + t*4);
            float4 o;
            o.x = __uint_as_float(f2tf(v.x)); o.y = __uint_as_float(f2tf(v.y));
            o.z = __uint_as_float(f2tf(v.z)); o.w = __uint_as_float(f2tf(v.w));
            *(float4*)(dst + t*4) = o;
        }
    }
}

__global__ __launch_bounds__(256, 1) void flash_mma(const float* __restrict__ t2,
                                                    float* __restrict__ out)
{
    extern __shared__ float sm[];
    int tid = threadIdx.x, w = tid >> 5, lane = tid & 31;
    int g = lane >> 2, tg = lane & 3;
    int qt = blockIdx.x, bh = blockIdx.y;
    int b = bh >> 3, h = bh & 7;
    const float* Qb = g_Pqs + ((size_t)b*NTOK + h*512)*512;
    const float* Kb = g_Pks + ((size_t)b*NTOK + h*512)*512;
    const float* Vb = g_Pvs + ((size_t)b*NTOK + h*512)*128;
    float qscale = 0.125f * t2[h] * 1.4426950408889634f;

    int q0 = w << 4;
    uint32_t qa[8][4];
    {
        const float* qr0 = Qb + (size_t)(qt*128 + q0 + g)*64;
        const float* qr1 = qr0 + 8*64;
        #pragma unroll
        for (int ks = 0; ks < 8; ks++) {
            qa[ks][0] = f2tf(qr0[ks*8 + tg]     * qscale);
            qa[ks][1] = f2tf(qr1[ks*8 + tg]     * qscale);
            qa[ks][2] = f2tf(qr0[ks*8 + tg + 4] * qscale);
            qa[ks][3] = f2tf(qr1[ks*8 + tg + 4] * qscale);
        }
    }

    float Ofr[2][4];
    #pragma unroll
    for (int n = 0; n < 2; n++)
        #pragma unroll
        for (int e = 0; e < 4; e++) Ofr[n][e] = 0.f;
    float l0 = 0.f, l1 = 0.f;

    load_kchunk(sm, Kb, 0, tid, 0);
    load_vchunk(sm, Vb, 0, tid, 0);
    __syncthreads();

    float* Psm = sm + POFF;
    uint32_t prow0 = (q0 + g)*KSTR, prow1 = (q0 + g + 8)*KSTR;

    #pragma unroll 1
    for (int c = 0; c < 64; c++) {
        int cur = c & 1;
        if (c < 63) {
            load_kchunk(sm, Kb, (c+1) << 6, tid, cur ^ 1);
            load_vchunk(sm, Vb, (c+1) << 6, tid, cur ^ 1);
        }
        const uint32_t* Kc = (const uint32_t*)(sm + KOFF(cur));
        const uint32_t* Vc = (const uint32_t*)(sm + VOFF(cur));

        float sfr[8][4];
        #pragma unroll
        for (int nt = 0; nt < 8; nt++) {
            sfr[nt][0] = sfr[nt][1] = sfr[nt][2] = sfr[nt][3] = 0.f;
            const uint32_t* krow = Kc + (nt*8 + g)*KSTR;
            #pragma unroll
            for (int ks = 0; ks < 8; ks++)
                mma8(sfr[nt], qa[ks], krow[ks*8 + tg], krow[ks*8 + tg + 4]);
        }
        float rs0 = 0.f, rs1 = 0.f;
        #pragma unroll
        for (int nt = 0; nt < 8; nt++) {
            float p0 = ex2f(sfr[nt][0]), p1 = ex2f(sfr[nt][1]);
            float p2 = ex2f(sfr[nt][2]), p3 = ex2f(sfr[nt][3]);
            rs0 += p0 + p1; rs1 += p2 + p3;
            float2 v0, v1;
            v0.x = __uint_as_float(f2tf(p0)); v0.y = __uint_as_float(f2tf(p1));
            v1.x = __uint_as_float(f2tf(p2)); v1.y = __uint_as_float(f2tf(p3));
            *(float2*)&Psm[prow0 + nt*8 + 2*tg] = v0;
            *(float2*)&Psm[prow1 + nt*8 + 2*tg] = v1;
        }
        rs0 += __shfl_xor_sync(0xffffffffu, rs0, 1);
        rs0 += __shfl_xor_sync(0xffffffffu, rs0, 2);
        rs1 += __shfl_xor_sync(0xffffffffu, rs1, 1);
        rs1 += __shfl_xor_sync(0xffffffffu, rs1, 2);
        l0 += rs0; l1 += rs1;
        __syncthreads();

        const uint32_t* Pu = (const uint32_t*)Psm;
        #pragma unroll
        for (int ks = 0; ks < 8; ks++) {
            uint32_t ap[4];
            ap[0] = Pu[prow0 + ks*8 + tg];
            ap[1] = Pu[prow1 + ks*8 + tg];
            ap[2] = Pu[prow0 + ks*8 + tg + 4];
            ap[3] = Pu[prow1 + ks*8 + tg + 4];
            const uint32_t* v0 = Vc + (ks*8 + tg)*VSTR;
            const uint32_t* v1 = Vc + (ks*8 + tg + 4)*VSTR;
            mma8(Ofr[0], ap, v0[g],     v1[g]);
            mma8(Ofr[1], ap, v0[g + 8], v1[g + 8]);
        }
        __syncthreads();
    }

    float inv0 = 1.f / l0, inv1 = 1.f / l1;
    int n_g  = qt*128 + q0 + g;
    int n_g8 = n_g + 8;
    float* op0 = out + ((size_t)b*NTOK + h*512 + (n_g  >> 3))*640 + 512 + (n_g  & 7)*16;
    float* op1 = out + ((size_t)b*NTOK + h*512 + (n_g8 >> 3))*640 + 512 + (n_g8 & 7)*16;
    #pragma unroll
    for (int nt = 0; nt < 2; nt++) {
        int cbase = nt*8 + 2*tg;
        float2 a, c2;
        a.x  = Ofr[nt][0]*inv0; a.y  = Ofr[nt][1]*inv0;
        c2.x = Ofr[nt][2]*inv1; c2.y = Ofr[nt][3]*inv1;
        *(float2*)(op0 + cbase) = a;
        *(float2*)(op1 + cbase) = c2;
    }
}

// =================== launch ===================
extern "C" void kernel_launch(void* const* d_in, const int* in_sizes, int n_in,
                              void* d_out, int out_size)
{
    const float* s_in = (const float*)d_in[0];
    const float* h_in = (const float*)d_in[1];
    const float* sh   = (const float*)d_in[2];
    const float* t1   = (const float*)d_in[3];
    const float* t2   = (const float*)d_in[4];
    const float* Wqc  = (const float*)d_in[5];
    const float* Wqs  = (const float*)d_in[6];
    const float* Wkc  = (const float*)d_in[7];
    const float* Wvc  = (const float*)d_in[8];
    const float* Wks  = (const float*)d_in[9];
    const float* Wvs  = (const float*)d_in[10];
    float* out = (float*)d_out;

    cudaFuncSetAttribute(flash_mma, cudaFuncAttributeMaxDynamicSharedMemorySize, FSMEM);

    gemm_proj_tc<<<dim3(20,64), 256>>>(s_in, sh, Wqs, Wkc, Wvc, Wks, Wqc);
    gemm_vs_tc<<<64, 256>>>(h_in, Wvs);
    flash_mma<<<dim3(32,16), 256, FSMEM>>>(t2, out);
    ca_scores<<<dim3(16,16), 256>>>();
    ca_reduce<<<16, 64>>>(t1);
    ca_out<<<dim3(64,16), 256>>>(out);
}

// round 6
// speedup vs baseline: 2.9411x; 1.0404x over previous
#include <cuda_runtime.h>
#include <math.h>
#include <stdint.h>

#define NB 2
#define NTOK 4096

__device__ float g_Pqc[8192*512];
__device__ float g_Pqs[8192*512];
__device__ float g_Pkc[8192*512];
__device__ float g_Pvc[8192*512];
__device__ float g_Pks[8192*512];
__device__ float g_Pvs[8192*128];
__device__ float g_Sca[16*16*64*64];
__device__ float g_Pca[16*64*64];

// =================== helpers ===================
__device__ __forceinline__ uint32_t f2tf(float x) {
    uint32_t r; asm("cvt.rna.tf32.f32 %0, %1;" : "=r"(r) : "f"(x)); return r;
}
__device__ __forceinline__ float ex2f(float x) {
    float r; asm("ex2.approx.ftz.f32 %0, %1;" : "=f"(r) : "f"(x)); return r;
}
__device__ __forceinline__ void mma8(float* d, const uint32_t* a, uint32_t b0, uint32_t b1) {
    asm volatile(
        "mma.sync.aligned.m16n8k8.row.col.f32.tf32.tf32.f32 "
        "{%0,%1,%2,%3},{%4,%5,%6,%7},{%8,%9},{%0,%1,%2,%3};"
        : "+f"(d[0]), "+f"(d[1]), "+f"(d[2]), "+f"(d[3])
        : "r"(a[0]), "r"(a[1]), "r"(a[2]), "r"(a[3]), "r"(b0), "r"(b1));
}
__device__ __forceinline__ uint32_t smem_u32(const void* p) {
    uint32_t a;
    asm("{ .reg .u64 t; cvta.to.shared.u64 t, %1; cvt.u32.u64 %0, t; }" : "=r"(a) : "l"(p));
    return a;
}
__device__ __forceinline__ void cpasync16(uint32_t dst, const void* src) {
    asm volatile("cp.async.ca.shared.global [%0], [%1], 16;" :: "r"(dst), "l"(src));
}
#define CP_COMMIT() asm volatile("cp.async.commit_group;" ::: "memory")
#define CP_WAIT1()  asm volatile("cp.async.wait_group 1;" ::: "memory")
#define CP_WAIT0()  asm volatile("cp.async.wait_group 0;" ::: "memory")

// =================== tf32 TC GEMM, cp.async double-buffered ===================
// C = A(MxK) @ W(OxK)^T ; 128x128 CTA tile, K-chunk 16, 8 warps of 64x32.
template<int K, int O>
__device__ __forceinline__ void gemm_tc_tile(const float* __restrict__ A,
                                             const float* __restrict__ W,
                                             float* __restrict__ C,
                                             int m0, int o0)
{
    __shared__ float sA[2][128*20];
    __shared__ float sW[2][128*20];
    const int NC = K / 16;
    int tid = threadIdx.x, w = tid >> 5, lane = tid & 31;
    int g = lane >> 2, tg = lane & 3;
    int wm = w >> 2, wn = w & 3;
    int pr = tid >> 1, pc = (tid & 1) << 3;     // copy: row pr, 8 floats at pc
    const float* Ap = A + (size_t)(m0 + pr) * K + pc;
    const float* Wp = W + (size_t)(o0 + pr) * K + pc;
    uint32_t sAb[2], sWb[2];
    sAb[0] = smem_u32(&sA[0][pr*20 + pc]); sAb[1] = smem_u32(&sA[1][pr*20 + pc]);
    sWb[0] = smem_u32(&sW[0][pr*20 + pc]); sWb[1] = smem_u32(&sW[1][pr*20 + pc]);

    float acc[4][4][4];
    #pragma unroll
    for (int mt = 0; mt < 4; mt++)
        #pragma unroll
        for (int nt = 0; nt < 4; nt++)
            #pragma unroll
            for (int e = 0; e < 4; e++) acc[mt][nt][e] = 0.f;

    // prefetch chunk 0 into buf 0
    cpasync16(sAb[0],      Ap);
    cpasync16(sAb[0] + 16, Ap + 4);
    cpasync16(sWb[0],      Wp);
    cpasync16(sWb[0] + 16, Wp + 4);
    CP_COMMIT();

    #pragma unroll 1
    for (int c = 0; c < NC; c++) {
        int cur = c & 1;
        if (c + 1 < NC) {
            int nxt = cur ^ 1;
            const float* ap = Ap + (c+1)*16;
            const float* wp = Wp + (c+1)*16;
            cpasync16(sAb[nxt],      ap);
            cpasync16(sAb[nxt] + 16, ap + 4);
            cpasync16(sWb[nxt],      wp);
            cpasync16(sWb[nxt] + 16, wp + 4);
            CP_COMMIT();
            CP_WAIT1();
        } else {
            CP_WAIT0();
        }
        __syncthreads();
        const float* cA = sA[cur];
        const float* cW = sW[cur];
        #pragma unroll
        for (int ks = 0; ks < 2; ks++) {
            uint32_t af[4][4], bf[4][2];
            #pragma unroll
            for (int mt = 0; mt < 4; mt++) {
                int rb = wm*64 + mt*16;
                af[mt][0] = f2tf(cA[(rb+g  )*20 + ks*8 + tg]);
                af[mt][1] = f2tf(cA[(rb+g+8)*20 + ks*8 + tg]);
                af[mt][2] = f2tf(cA[(rb+g  )*20 + ks*8 + tg + 4]);
                af[mt][3] = f2tf(cA[(rb+g+8)*20 + ks*8 + tg + 4]);
            }
            #pragma unroll
            for (int nt = 0; nt < 4; nt++) {
                int rb = wn*32 + nt*8 + g;
                bf[nt][0] = f2tf(cW[rb*20 + ks*8 + tg]);
                bf[nt][1] = f2tf(cW[rb*20 + ks*8 + tg + 4]);
            }
            #pragma unroll
            for (int mt = 0; mt < 4; mt++)
                #pragma unroll
                for (int nt = 0; nt < 4; nt++)
                    mma8(acc[mt][nt], af[mt], bf[nt][0], bf[nt][1]);
        }
        __syncthreads();
    }
    #pragma unroll
    for (int mt = 0; mt < 4; mt++) {
        int r = m0 + wm*64 + mt*16 + g;
        #pragma unroll
        for (int nt = 0; nt < 4; nt++) {
            float* cp = C + (size_t)r*O + o0 + wn*32 + nt*8 + 2*tg;
            *(float2*)cp         = make_float2(acc[mt][nt][0], acc[mt][nt][1]);
            *(float2*)(cp + 8*O) = make_float2(acc[mt][nt][2], acc[mt][nt][3]);
        }
    }
}

__global__ __launch_bounds__(256, 2) void gemm_proj_tc(
    const float* __restrict__ s_in, const float* __restrict__ sh_in,
    const float* __restrict__ Wqs, const float* __restrict__ Wkc,
    const float* __restrict__ Wvc, const float* __restrict__ Wks,
    const float* __restrict__ Wqc)
{
    int job = blockIdx.x >> 2;
    int ot  = blockIdx.x & 3;
    int m0  = blockIdx.y << 7;
    const float* A; const float* W; float* C;
    switch (job) {
        case 0: A = sh_in; W = Wqs; C = g_Pqs; break;
        case 1: A = sh_in; W = Wkc; C = g_Pkc; break;
        case 2: A = sh_in; W = Wvc; C = g_Pvc; break;
        case 3: A = sh_in; W = Wks; C = g_Pks; break;
        default: A = s_in; W = Wqc; C = g_Pqc; break;
    }
    gemm_tc_tile<512,512>(A, W, C, m0, ot << 7);
}

__global__ __launch_bounds__(256, 2) void gemm_vs_tc(
    const float* __restrict__ h_in, const float* __restrict__ Wvs)
{
    gemm_tc_tile<128,128>(h_in, Wvs, g_Pvs, blockIdx.x << 7, 0);
}

// =================== channel attention ===================
__global__ __launch_bounds__(256) void ca_scores()
{
    __shared__ float Qs[32][68];
    __shared__ float Ks[32][68];
    int slice = blockIdx.x;
    int bh    = blockIdx.y;
    int b = bh >> 3, h = bh & 7;
    const float* Qc = g_Pqc + ((size_t)b*NTOK + h*512) * 512;
    const float* Kc = g_Pkc + ((size_t)b*NTOK + h*512) * 512;
    int tid = threadIdx.x;
    int lr = tid >> 3, lc = (tid & 7) << 3;
    int i0 = (tid >> 4) << 2, j0 = (tid & 15) << 2;
    float acc[4][4];
    #pragma unroll
    for (int i = 0; i < 4; i++)
        #pragma unroll
        for (int j = 0; j < 4; j++) acc[i][j] = 0.f;
    #pragma unroll 1
    for (int nt = 0; nt < 8; nt++) {
        int nb = slice*256 + (nt << 5);
        const float* qp = Qc + (size_t)(nb + lr)*64 + lc;
        const float* kp = Kc + (size_t)(nb + lr)*64 + lc;
        float4 q0 = *(const float4*)qp, q1 = *(const float4*)(qp+4);
        float4 k0 = *(const float4*)kp, k1 = *(const float4*)(kp+4);
        __syncthreads();
        *(float4*)&Qs[lr][lc] = q0; *(float4*)&Qs[lr][lc+4] = q1;
        *(float4*)&Ks[lr][lc] = k0; *(float4*)&Ks[lr][lc+4] = k1;
        __syncthreads();
        #pragma unroll 8
        for (int nn = 0; nn < 32; nn++) {
            float4 q = *(const float4*)&Qs[nn][i0];
            float4 k = *(const float4*)&Ks[nn][j0];
            float qa[4] = {q.x,q.y,q.z,q.w};
            float ka[4] = {k.x,k.y,k.z,k.w};
            #pragma unroll
            for (int i = 0; i < 4; i++)
                #pragma unroll
                for (int j = 0; j < 4; j++)
                    acc[i][j] = fmaf(qa[i], ka[j], acc[i][j]);
        }
    }
    float* dst = g_Sca + ((size_t)(bh*16 + slice)*64)*64;
    #pragma unroll
    for (int i = 0; i < 4; i++)
        *(float4*)&dst[(i0+i)*64 + j0] = make_float4(acc[i][0],acc[i][1],acc[i][2],acc[i][3]);
}

__global__ void ca_reduce(const float* __restrict__ temp)
{
    int bh = blockIdx.x;
    int h  = bh & 7;
    int i  = threadIdx.x;
    float scale = 0.125f * temp[h];
    float row[64];
    #pragma unroll
    for (int j = 0; j < 64; j++) {
        float s = 0.f;
        #pragma unroll
        for (int p = 0; p < 16; p++)
            s += g_Sca[((size_t)(bh*16+p)*64 + i)*64 + j];
        row[j] = s * scale;
    }
    float m = row[0];
    #pragma unroll
    for (int j = 1; j < 64; j++) m = fmaxf(m, row[j]);
    float sum = 0.f;
    #pragma unroll
    for (int j = 0; j < 64; j++) { row[j] = __expf(row[j]-m); sum += row[j]; }
    float inv = 1.f / sum;
    #pragma unroll
    for (int j = 0; j < 64; j++)
        g_Pca[((size_t)bh*64 + i)*64 + j] = row[j]*inv;
}

__global__ __launch_bounds__(256) void ca_out(float* __restrict__ out)
{
    __shared__ float Pts[64][68];
    __shared__ float Vt[64][68];
    int mt = blockIdx.x;
    int bh = blockIdx.y;
    int b = bh >> 3, h = bh & 7;
    int tid = threadIdx.x;
    {
        int i  = tid & 63;
        int jc = (tid >> 6) << 4;
        const float* pp = g_Pca + ((size_t)bh*64 + i)*64 + jc;
        #pragma unroll
        for (int t = 0; t < 4; t++) {
            float4 v = *(const float4*)(pp + t*4);
            Pts[jc+t*4+0][i] = v.x; Pts[jc+t*4+1][i] = v.y;
            Pts[jc+t*4+2][i] = v.z; Pts[jc+t*4+3][i] = v.w;
        }
    }
    {
        int mm = tid & 63;
        int jc = (tid >> 6) << 4;
        const float* vp = g_Pvc + ((size_t)b*NTOK + h*512)*512 + (size_t)(mt*64 + mm)*64 + jc;
        #pragma unroll
        for (int t = 0; t < 4; t++) {
            float4 v = *(const float4*)(vp + t*4);
            Vt[jc+t*4+0][mm] = v.x; Vt[jc+t*4+1][mm] = v.y;
            Vt[jc+t*4+2][mm] = v.z; Vt[jc+t*4+3][mm] = v.w;
        }
    }
    __syncthreads();
    int i0 = (tid >> 4) << 2, m0 = (tid & 15) << 2;
    float acc[4][4];
    #pragma unroll
    for (int i = 0; i < 4; i++)
        #pragma unroll
        for (int j = 0; j < 4; j++) acc[i][j] = 0.f;
    #pragma unroll 8
    for (int j = 0; j < 64; j++) {
        float4 p = *(const float4*)&Pts[j][i0];
        float4 v = *(const float4*)&Vt[j][m0];
        float pa[4] = {p.x,p.y,p.z,p.w};
        float va[4] = {v.x,v.y,v.z,v.w};
        #pragma unroll
        for (int i = 0; i < 4; i++)
            #pragma unroll
            for (int m = 0; m < 4; m++)
                acc[i][m] = fmaf(pa[i], va[m], acc[i][m]);
    }
    int rowoff  = mt >> 3;
    int colbase = (mt & 7)*64 + m0;
    #pragma unroll
    for (int i = 0; i < 4; i++) {
        int row = h*512 + (i0+i)*8 + rowoff;
        float* op = out + ((size_t)b*NTOK + row)*640 + colbase;
        *(float4*)op = make_float4(acc[i][0],acc[i][1],acc[i][2],acc[i][3]);
    }
}

// =================== spatial flash attention: mma.sync tf32 ===================
#define KSTR 68
#define VSTR 20
#define KOFF(b) ((b)*4352)
#define VOFF(b) (8704 + (b)*1280)
#define POFF 11264
#define FSMEM ((11264 + 128*68) * 4)

__device__ __forceinline__ void load_kchunk(float* sm, const float* __restrict__ Kb,
                                            int kb, int tid, int buf)
{
    int j = tid >> 2, cg = (tid & 3) << 4;
    const float* kp = Kb + (size_t)(kb + j)*64 + cg;
    float* dst = sm + KOFF(buf) + j*KSTR + cg;
    #pragma unroll
    for (int t = 0; t < 4; t++) {
        float4 v = *(const float4*)(kp + t*4);
        float4 o;
        o.x = __uint_as_float(f2tf(v.x)); o.y = __uint_as_float(f2tf(v.y));
        o.z = __uint_as_float(f2tf(v.z)); o.w = __uint_as_float(f2tf(v.w));
        *(float4*)(dst + t*4) = o;
    }
}

__device__ __forceinline__ void load_vchunk(float* sm, const float* __restrict__ Vb,
                                            int kb, int tid, int buf)
{
    if (tid < 128) {
        int j = tid >> 1, cv = (tid & 1) << 3;
        const float* vp = Vb + (size_t)(kb + j)*16 + cv;
        float* dst = sm + VOFF(buf) + j*VSTR + cv;
        #pragma unroll
        for (int t = 0; t < 2; t++) {
            float4 v = *(const float4*)(vp + t*4);
            float4 o;
            o.x = __uint_as_float(f2tf(v.x)); o.y = __uint_as_float(f2tf(v.y));
            o.z = __uint_as_float(f2tf(v.z)); o.w = __uint_as_float(f2tf(v.w));
            *(float4*)(dst + t*4) = o;
        }
    }
}

__global__ __launch_bounds__(256, 1) void flash_mma(const float* __restrict__ t2,
                                                    float* __restrict__ out)
{
    extern __shared__ float sm[];
    int tid = threadIdx.x, w = tid >> 5, lane = tid & 31;
    int g = lane >> 2, tg = lane & 3;
    int qt = blockIdx.x, bh = blockIdx.y;
    int b = bh >> 3, h = bh & 7;
    const float* Qb = g_Pqs + ((size_t)b*NTOK + h*512)*512;
    const float* Kb = g_Pks + ((size_t)b*NTOK + h*512)*512;
    const float* Vb = g_Pvs + ((size_t)b*NTOK + h*512)*128;
    float qscale = 0.125f * t2[h] * 1.4426950408889634f;

    int q0 = w << 4;
    uint32_t qa[8][4];
    {
        const float* qr0 = Qb + (size_t)(qt*128 + q0 + g)*64;
        const float* qr1 = qr0 + 8*64;
        #pragma unroll
        for (int ks = 0; ks < 8; ks++) {
            qa[ks][0] = f2tf(qr0[ks*8 + tg]     * qscale);
            qa[ks][1] = f2tf(qr1[ks*8 + tg]     * qscale);
            qa[ks][2] = f2tf(qr0[ks*8 + tg + 4] * qscale);
            qa[ks][3] = f2tf(qr1[ks*8 + tg + 4] * qscale);
        }
    }

    float Ofr[2][4];
    #pragma unroll
    for (int n = 0; n < 2; n++)
        #pragma unroll
        for (int e = 0; e < 4; e++) Ofr[n][e] = 0.f;
    float l0 = 0.f, l1 = 0.f;

    load_kchunk(sm, Kb, 0, tid, 0);
    load_vchunk(sm, Vb, 0, tid, 0);
    __syncthreads();

    float* Psm = sm + POFF;
    uint32_t prow0 = (q0 + g)*KSTR, prow1 = (q0 + g + 8)*KSTR;

    #pragma unroll 1
    for (int c = 0; c < 64; c++) {
        int cur = c & 1;
        if (c < 63) {
            load_kchunk(sm, Kb, (c+1) << 6, tid, cur ^ 1);
            load_vchunk(sm, Vb, (c+1) << 6, tid, cur ^ 1);
        }
        const uint32_t* Kc = (const uint32_t*)(sm + KOFF(cur));
        const uint32_t* Vc = (const uint32_t*)(sm + VOFF(cur));

        float sfr[8][4];
        #pragma unroll
        for (int nt = 0; nt < 8; nt++) {
            sfr[nt][0] = sfr[nt][1] = sfr[nt][2] = sfr[nt][3] = 0.f;
            const uint32_t* krow = Kc + (nt*8 + g)*KSTR;
            #pragma unroll
            for (int ks = 0; ks < 8; ks++)
                mma8(sfr[nt], qa[ks], krow[ks*8 + tg], krow[ks*8 + tg + 4]);
        }
        float rs0 = 0.f, rs1 = 0.f;
        #pragma unroll
        for (int nt = 0; nt < 8; nt++) {
            float p0 = ex2f(sfr[nt][0]), p1 = ex2f(sfr[nt][1]);
            float p2 = ex2f(sfr[nt][2]), p3 = ex2f(sfr[nt][3]);
            rs0 += p0 + p1; rs1 += p2 + p3;
            float2 v0, v1;
            v0.x = __uint_as_float(f2tf(p0)); v0.y = __uint_as_float(f2tf(p1));
            v1.x = __uint_as_float(f2tf(p2)); v1.y = __uint_as_float(f2tf(p3));
            *(float2*)&Psm[prow0 + nt*8 + 2*tg] = v0;
            *(float2*)&Psm[prow1 + nt*8 + 2*tg] = v1;
        }
        rs0 += __shfl_xor_sync(0xffffffffu, rs0, 1);
        rs0 += __shfl_xor_sync(0xffffffffu, rs0, 2);
        rs1 += __shfl_xor_sync(0xffffffffu, rs1, 1);
        rs1 += __shfl_xor_sync(0xffffffffu, rs1, 2);
        l0 += rs0; l1 += rs1;
        __syncthreads();

        const uint32_t* Pu = (const uint32_t*)Psm;
        #pragma unroll
        for (int ks = 0; ks < 8; ks++) {
            uint32_t ap[4];
            ap[0] = Pu[prow0 + ks*8 + tg];
            ap[1] = Pu[prow1 + ks*8 + tg];
            ap[2] = Pu[prow0 + ks*8 + tg + 4];
            ap[3] = Pu[prow1 + ks*8 + tg + 4];
            const uint32_t* v0 = Vc + (ks*8 + tg)*VSTR;
            const uint32_t* v1 = Vc + (ks*8 + tg + 4)*VSTR;
            mma8(Ofr[0], ap, v0[g],     v1[g]);
            mma8(Ofr[1], ap, v0[g + 8], v1[g + 8]);
        }
        __syncthreads();
    }

    float inv0 = 1.f / l0, inv1 = 1.f / l1;
    int n_g  = qt*128 + q0 + g;
    int n_g8 = n_g + 8;
    float* op0 = out + ((size_t)b*NTOK + h*512 + (n_g  >> 3))*640 + 512 + (n_g  & 7)*16;
    float* op1 = out + ((size_t)b*NTOK + h*512 + (n_g8 >> 3))*640 + 512 + (n_g8 & 7)*16;
    #pragma unroll
    for (int nt = 0; nt < 2; nt++) {
        int cbase = nt*8 + 2*tg;
        float2 a, c2;
        a.x  = Ofr[nt][0]*inv0; a.y  = Ofr[nt][1]*inv0;
        c2.x = Ofr[nt][2]*inv1; c2.y = Ofr[nt][3]*inv1;
        *(float2*)(op0 + cbase) = a;
        *(float2*)(op1 + cbase) = c2;
    }
}

// =================== launch ===================
extern "C" void kernel_launch(void* const* d_in, const int* in_sizes, int n_in,
                              void* d_out, int out_size)
{
    const float* s_in = (const float*)d_in[0];
    const float* h_in = (const float*)d_in[1];
    const float* sh   = (const float*)d_in[2];
    const float* t1   = (const float*)d_in[3];
    const float* t2   = (const float*)d_in[4];
    const float* Wqc  = (const float*)d_in[5];
    const float* Wqs  = (const float*)d_in[6];
    const float* Wkc  = (const float*)d_in[7];
    const float* Wvc  = (const float*)d_in[8];
    const float* Wks  = (const float*)d_in[9];
    const float* Wvs  = (const float*)d_in[10];
    float* out = (float*)d_out;

    cudaFuncSetAttribute(flash_mma, cudaFuncAttributeMaxDynamicSharedMemorySize, FSMEM);

    gemm_proj_tc<<<dim3(20,64), 256>>>(s_in, sh, Wqs, Wkc, Wvc, Wks, Wqc);
    gemm_vs_tc<<<64, 256>>>(h_in, Wvs);
    flash_mma<<<dim3(32,16), 256, FSMEM>>>(t2, out);
    ca_scores<<<dim3(16,16), 256>>>();
    ca_reduce<<<16, 64>>>(t1);
    ca_out<<<dim3(64,16), 256>>>(out);
}